// round 2
// baseline (speedup 1.0000x reference)
#include <cuda_runtime.h>
#include <math.h>

// Fixed shapes: (B,H,W,C,T) = (64,80,80,80,50)
#define BB    64
#define HH    80
#define WW    80
#define HWC   (HH*WW)          // 6400
#define CC    80
#define DD    (5+CC)           // 85
#define TT    50
#define NT    (BB*TT)          // 3200
#define NCELL (BB*HWC)         // 409600

#define NBLK  200
#define NTHR  1024             // NBLK*NTHR*2 == NCELL exactly

#define LAMBDA_COORD 5.0
#define LAMBDA_NOOBJ 0.5

// Per-block partials: every slot is written on every replay -> no init kernel.
__device__ float g_conf_part[NBLK];
__device__ float g_coord_part[BB];
__device__ float g_cls_part[BB];
__device__ float g_obj_part[BB];
__device__ float g_corr_part[BB];
__device__ int   g_cnt_part[BB];
__device__ unsigned int g_counter = 0;   // reset by last block each replay

__device__ __forceinline__ float softplus_pos(float x) {
    return log1pf(__expf(-fabsf(x))) + fmaxf(x, 0.0f);
}

// Block reduce (1024 threads, 32 warps). Result valid in thread 0.
__device__ __forceinline__ double blockReduceD(double v, double* sd) {
    int lane = threadIdx.x & 31, w = threadIdx.x >> 5;
    #pragma unroll
    for (int o = 16; o > 0; o >>= 1) v += __shfl_xor_sync(0xffffffffu, v, o);
    if (lane == 0) sd[w] = v;
    __syncthreads();
    v = (threadIdx.x < 32) ? sd[threadIdx.x] : 0.0;
    if (w == 0) {
        #pragma unroll
        for (int o = 16; o > 0; o >>= 1) v += __shfl_xor_sync(0xffffffffu, v, o);
    }
    __syncthreads();   // safe reuse of sd
    return v;
}

__global__ void __launch_bounds__(NTHR)
k_fused(const float* __restrict__ pred, const float* __restrict__ targets,
        float* __restrict__ out) {
    const int tid = threadIdx.x;
    const int blk = blockIdx.x;
    const int lane = tid & 31;
    const int warp = tid >> 5;

    // ---- issue the two independent conf loads first (MLP=2) ----
    const int i0 = blk * (2 * NTHR) + tid;
    const int i1 = i0 + NTHR;
    const float c0 = __ldg(&pred[(size_t)i0 * DD + 4]);
    const float c1 = __ldg(&pred[(size_t)i1 * DD + 4]);

    __shared__ int   s_cell[TT];
    __shared__ float s_tx[TT], s_ty[TT], s_tw[TT], s_th[TT];
    __shared__ int   s_cid[TT];
    __shared__ float s_c[32], s_l[32], s_o[32], s_r[32];
    __shared__ int   s_n[32];
    __shared__ double sd[32];
    __shared__ bool  isLast;

    // ---- target branch: blocks 0..63, one batch each ----
    if (blk < BB) {
        if (tid < TT) {
            const float* tg = targets + ((size_t)blk * TT + tid) * 5;
            float cx = tg[1], cy = tg[2], w = tg[3], h = tg[4];
            int gx = (int)floorf(cx * WW);
            int gy = (int)floorf(cy * HH);
            s_cell[tid] = gy * WW + gx;
            s_tx[tid] = cx * WW - (float)gx;
            s_ty[tid] = cy * HH - (float)gy;
            s_tw[tid] = logf(w * WW + 1e-16f);
            s_th[tid] = logf(h * HH + 1e-16f);
            s_cid[tid] = (int)tg[0];
        }
        __syncthreads();

        float coordv = 0.f, clsv = 0.f, objv = 0.f, corrv = 0.f;
        int cntv = 0;
        for (int t = warp; t < TT; t += 32) {
            const int cell = s_cell[t];
            const float* g = pred + ((size_t)blk * HWC + cell) * DD;
            // warp-cooperative logsumexp over 80 classes
            float v0 = __ldg(&g[5 + lane]);
            float v1 = __ldg(&g[5 + 32 + lane]);
            float v2 = (lane < 16) ? __ldg(&g[5 + 64 + lane]) : -1e30f;
            float m = fmaxf(fmaxf(v0, v1), v2);
            #pragma unroll
            for (int o = 16; o > 0; o >>= 1)
                m = fmaxf(m, __shfl_xor_sync(0xffffffffu, m, o));
            float s = expf(v0 - m) + expf(v1 - m) +
                      ((lane < 16) ? expf(v2 - m) : 0.0f);
            #pragma unroll
            for (int o = 16; o > 0; o >>= 1)
                s += __shfl_xor_sync(0xffffffffu, s, o);

            if (lane == 0) {
                clsv += -(__ldg(&g[5 + s_cid[t]]) - m - logf(s));
                float sx = 1.0f / (1.0f + expf(-__ldg(&g[0])));
                float sy = 1.0f / (1.0f + expf(-__ldg(&g[1])));
                float dx = sx - s_tx[t], dy = sy - s_ty[t];
                float dw = __ldg(&g[2]) - s_tw[t], dh = __ldg(&g[3]) - s_th[t];
                coordv += 0.5f * (dx * dx + dy * dy) + 0.5f * (dw * dw + dh * dh);
                // first-occurrence dedup within this batch
                bool uniq = true;
                for (int j = 0; j < t; j++)
                    if (s_cell[j] == cell) { uniq = false; break; }
                if (uniq) {
                    cntv++;
                    float cl = __ldg(&g[4]);
                    float base = log1pf(expf(-fabsf(cl)));
                    objv  += base + fmaxf(-cl, 0.0f);   // softplus(-cl)
                    corrv += base + fmaxf( cl, 0.0f);   // softplus(cl)
                }
            }
        }
        if (lane == 0) {
            s_c[warp] = coordv; s_l[warp] = clsv;
            s_o[warp] = objv;   s_r[warp] = corrv;
            s_n[warp] = cntv;
        }
        __syncthreads();
        if (tid == 0) {
            float a = 0, b = 0, c = 0, d = 0; int n = 0;
            #pragma unroll
            for (int i = 0; i < 32; i++) {
                a += s_c[i]; b += s_l[i]; c += s_o[i]; d += s_r[i]; n += s_n[i];
            }
            g_coord_part[blk] = a; g_cls_part[blk] = b;
            g_obj_part[blk] = c;   g_corr_part[blk] = d;
            g_cnt_part[blk] = n;
        }
        __syncthreads();
    }

    // ---- conf partial: reduce softplus(c0)+softplus(c1) over the block ----
    {
        float s = softplus_pos(c0) + softplus_pos(c1);
        #pragma unroll
        for (int o = 16; o > 0; o >>= 1)
            s += __shfl_xor_sync(0xffffffffu, s, o);
        if (lane == 0) s_c[warp] = s;
        __syncthreads();
        if (tid == 0) {
            float t = 0;
            #pragma unroll
            for (int i = 0; i < 32; i++) t += s_c[i];
            g_conf_part[blk] = t;
        }
    }

    // ---- last block finalizes ----
    __threadfence();
    if (tid == 0) {
        unsigned old = atomicAdd(&g_counter, 1);
        isLast = (old == (unsigned)(NBLK - 1));
    }
    __syncthreads();
    if (!isLast) return;

    double confv  = (tid < NBLK) ? (double)g_conf_part[tid]  : 0.0;
    double coordv = (tid < BB)   ? (double)g_coord_part[tid] : 0.0;
    double clsv   = (tid < BB)   ? (double)g_cls_part[tid]   : 0.0;
    double objv   = (tid < BB)   ? (double)g_obj_part[tid]   : 0.0;
    double corrv  = (tid < BB)   ? (double)g_corr_part[tid]  : 0.0;
    double cntv   = (tid < BB)   ? (double)g_cnt_part[tid]   : 0.0;

    double alls  = blockReduceD(confv, sd);
    double coord = blockReduceD(coordv, sd);
    double cls   = blockReduceD(clsv, sd);
    double objs  = blockReduceD(objv, sd);
    double corr  = blockReduceD(corrv, sd);
    double cnt   = blockReduceD(cntv, sd);

    if (tid == 0) {
        int nobj = (int)(cnt + 0.5);
        double n_noobj = (double)(NCELL - nobj);
        double noobj_sum = alls - corr;
        double conf_obj = objs / (double)(nobj > 0 ? nobj : 1);
        double conf_noobj = noobj_sum / n_noobj;
        double num_obj = (double)NT;
        double total = LAMBDA_COORD * coord / num_obj
                     + conf_obj / num_obj
                     + LAMBDA_NOOBJ * conf_noobj / n_noobj
                     + cls / num_obj;
        out[0] = (float)total;
        g_counter = 0;   // reset for next graph replay
    }
}

extern "C" void kernel_launch(void* const* d_in, const int* in_sizes, int n_in,
                              void* d_out, int out_size) {
    const float* pred    = (const float*)d_in[0];
    const float* targets = (const float*)d_in[1];
    float* out = (float*)d_out;
    (void)in_sizes; (void)n_in; (void)out_size;

    k_fused<<<NBLK, NTHR>>>(pred, targets, out);
}

// round 3
// speedup vs baseline: 1.0788x; 1.0788x over previous
#include <cuda_runtime.h>
#include <math.h>

// Fixed shapes: (B,H,W,C,T) = (64,80,80,80,50)
#define BB    64
#define HH    80
#define WW    80
#define HWC   (HH*WW)          // 6400
#define CC    80
#define DD    (5+CC)           // 85
#define TT    50
#define NT    (BB*TT)          // 3200
#define NCELL (BB*HWC)         // 409600

#define NBLK  148              // exactly one wave on 148 SMs
#define NTHR  1024
#define GSTRIDE (NBLK*NTHR)    // 151552
#define PER   3                // ceil(409600/151552)

#define LAMBDA_COORD 5.0
#define LAMBDA_NOOBJ 0.5

// Per-block partials: every slot written on every replay -> no init kernel.
__device__ float g_conf_part[NBLK];
__device__ float g_coord_part[BB];
__device__ float g_cls_part[BB];
__device__ float g_obj_part[BB];
__device__ float g_corr_part[BB];
__device__ int   g_cnt_part[BB];
__device__ unsigned int g_counter = 0;   // reset by last block each replay

__device__ __forceinline__ float softplus_pos(float x) {
    return log1pf(__expf(-fabsf(x))) + fmaxf(x, 0.0f);
}

__global__ void __launch_bounds__(NTHR)
k_fused(const float* __restrict__ pred, const float* __restrict__ targets,
        float* __restrict__ out) {
    const int tid = threadIdx.x;
    const int blk = blockIdx.x;
    const int lane = tid & 31;
    const int warp = tid >> 5;

    // ---- issue all PER independent conf loads up front (MLP) ----
    const int base = blk * NTHR + tid;
    float cv[PER];
    #pragma unroll
    for (int k = 0; k < PER; k++) {
        int i = base + k * GSTRIDE;
        cv[k] = (i < NCELL) ? __ldg(&pred[(size_t)i * DD + 4]) : 0.0f;
    }

    __shared__ int   s_cell[TT];
    __shared__ float s_tx[TT], s_ty[TT], s_tw[TT], s_th[TT];
    __shared__ int   s_cid[TT];
    __shared__ float s_c[32], s_l[32], s_o[32], s_r[32];
    __shared__ int   s_n[32];
    __shared__ double sd[32];
    __shared__ bool  isLast;

    // ---- target branch: blocks 0..63, one batch each (overlaps conf loads) ----
    if (blk < BB) {
        if (tid < TT) {
            const float* tg = targets + ((size_t)blk * TT + tid) * 5;
            float cx = tg[1], cy = tg[2], w = tg[3], h = tg[4];
            int gx = (int)floorf(cx * WW);
            int gy = (int)floorf(cy * HH);
            s_cell[tid] = gy * WW + gx;
            s_tx[tid] = cx * WW - (float)gx;
            s_ty[tid] = cy * HH - (float)gy;
            s_tw[tid] = logf(w * WW + 1e-16f);
            s_th[tid] = logf(h * HH + 1e-16f);
            s_cid[tid] = (int)tg[0];
        }
        __syncthreads();

        float coordv = 0.f, clsv = 0.f, objv = 0.f, corrv = 0.f;
        int cntv = 0;
        for (int t = warp; t < TT; t += 32) {
            const int cell = s_cell[t];
            const float* g = pred + ((size_t)blk * HWC + cell) * DD;
            // warp-cooperative logsumexp over 80 classes
            float v0 = __ldg(&g[5 + lane]);
            float v1 = __ldg(&g[5 + 32 + lane]);
            float v2 = (lane < 16) ? __ldg(&g[5 + 64 + lane]) : -1e30f;
            float m = fmaxf(fmaxf(v0, v1), v2);
            #pragma unroll
            for (int o = 16; o > 0; o >>= 1)
                m = fmaxf(m, __shfl_xor_sync(0xffffffffu, m, o));
            float s = __expf(v0 - m) + __expf(v1 - m) +
                      ((lane < 16) ? __expf(v2 - m) : 0.0f);
            #pragma unroll
            for (int o = 16; o > 0; o >>= 1)
                s += __shfl_xor_sync(0xffffffffu, s, o);

            if (lane == 0) {
                clsv += -(__ldg(&g[5 + s_cid[t]]) - m - logf(s));
                float sx = 1.0f / (1.0f + __expf(-__ldg(&g[0])));
                float sy = 1.0f / (1.0f + __expf(-__ldg(&g[1])));
                float dx = sx - s_tx[t], dy = sy - s_ty[t];
                float dw = __ldg(&g[2]) - s_tw[t], dh = __ldg(&g[3]) - s_th[t];
                coordv += 0.5f * (dx * dx + dy * dy) + 0.5f * (dw * dw + dh * dh);
                // first-occurrence dedup within this batch
                bool uniq = true;
                for (int j = 0; j < t; j++)
                    if (s_cell[j] == cell) { uniq = false; break; }
                if (uniq) {
                    cntv++;
                    float cl = __ldg(&g[4]);
                    float bse = log1pf(__expf(-fabsf(cl)));
                    objv  += bse + fmaxf(-cl, 0.0f);   // softplus(-cl)
                    corrv += bse + fmaxf( cl, 0.0f);   // softplus(cl)
                }
            }
        }
        if (lane == 0) {
            s_c[warp] = coordv; s_l[warp] = clsv;
            s_o[warp] = objv;   s_r[warp] = corrv;
            s_n[warp] = cntv;
        }
        __syncthreads();
        if (tid == 0) {
            float a = 0, b = 0, c = 0, d = 0; int n = 0;
            #pragma unroll
            for (int i = 0; i < 32; i++) {
                a += s_c[i]; b += s_l[i]; c += s_o[i]; d += s_r[i]; n += s_n[i];
            }
            g_coord_part[blk] = a; g_cls_part[blk] = b;
            g_obj_part[blk] = c;   g_corr_part[blk] = d;
            g_cnt_part[blk] = n;
        }
        __syncthreads();
    }

    // ---- conf partial: block-reduce sum of softplus over this thread's cells ----
    {
        float s = 0.0f;
        #pragma unroll
        for (int k = 0; k < PER; k++) {
            int i = base + k * GSTRIDE;
            if (i < NCELL) s += softplus_pos(cv[k]);
        }
        #pragma unroll
        for (int o = 16; o > 0; o >>= 1)
            s += __shfl_xor_sync(0xffffffffu, s, o);
        if (lane == 0) s_c[warp] = s;
        __syncthreads();
        if (tid == 0) {
            float t = 0;
            #pragma unroll
            for (int i = 0; i < 32; i++) t += s_c[i];
            g_conf_part[blk] = t;
        }
    }

    // ---- last block finalizes ----
    __threadfence();
    if (tid == 0) {
        unsigned old = atomicAdd(&g_counter, 1);
        isLast = (old == (unsigned)(NBLK - 1));
    }
    __syncthreads();
    if (!isLast) return;
    __threadfence();

    // 6 parallel warp reductions: warp 0 -> conf(148), warps 1..5 -> 64-elt arrays
    double r = 0.0;
    if (warp == 0) {
        for (int i = lane; i < NBLK; i += 32) r += (double)g_conf_part[i];
    } else if (warp == 1) {
        for (int i = lane; i < BB; i += 32) r += (double)g_coord_part[i];
    } else if (warp == 2) {
        for (int i = lane; i < BB; i += 32) r += (double)g_cls_part[i];
    } else if (warp == 3) {
        for (int i = lane; i < BB; i += 32) r += (double)g_obj_part[i];
    } else if (warp == 4) {
        for (int i = lane; i < BB; i += 32) r += (double)g_corr_part[i];
    } else if (warp == 5) {
        for (int i = lane; i < BB; i += 32) r += (double)g_cnt_part[i];
    }
    #pragma unroll
    for (int o = 16; o > 0; o >>= 1)
        r += __shfl_down_sync(0xffffffffu, r, o);
    if (lane == 0 && warp < 6) sd[warp] = r;
    __syncthreads();

    if (tid == 0) {
        double alls = sd[0], coord = sd[1], cls = sd[2];
        double objs = sd[3], corr = sd[4];
        int nobj = (int)(sd[5] + 0.5);
        double n_noobj = (double)(NCELL - nobj);
        double noobj_sum = alls - corr;
        double conf_obj = objs / (double)(nobj > 0 ? nobj : 1);
        double conf_noobj = noobj_sum / n_noobj;
        double num_obj = (double)NT;
        double total = LAMBDA_COORD * coord / num_obj
                     + conf_obj / num_obj
                     + LAMBDA_NOOBJ * conf_noobj / n_noobj
                     + cls / num_obj;
        out[0] = (float)total;
        g_counter = 0;   // reset for next graph replay
    }
}

extern "C" void kernel_launch(void* const* d_in, const int* in_sizes, int n_in,
                              void* d_out, int out_size) {
    const float* pred    = (const float*)d_in[0];
    const float* targets = (const float*)d_in[1];
    float* out = (float*)d_out;
    (void)in_sizes; (void)n_in; (void)out_size;

    k_fused<<<NBLK, NTHR>>>(pred, targets, out);
}